// round 2
// baseline (speedup 1.0000x reference)
#include <cuda_runtime.h>
#include <math.h>

// ---------------------------------------------------------------------------
// YOLOv3 loss, fused, one scalar output.
// Input order (setup_inputs dict insertion order — interleaved!):
//   d_in[0]=y_pred0  d_in[1]=y_true0
//   d_in[2]=y_pred1  d_in[3]=y_true1
//   d_in[4]=y_pred2  d_in[5]=y_true2
//   d_in[6]=target
// Layouts:
//   y_pred{i}: (32, 255, G, G)   float32, channel-major
//   y_true{i}: (32, 3, G, G, 85) float32, channel-contiguous per cell
//   target   : (32, 20, 5)       float32
// bce(sigmoid(x), t) == softplus(clamp(x,±C)) - t*clamp(x,±C),
//   C = ln((1-eps)/eps) = 16.118095  (exactly reproduces the eps p-clip)
// ---------------------------------------------------------------------------

#define CLIP_C 16.118095f
#define NBOX   20
#define NBATCH 32

__device__ __forceinline__ float bce_logit(float x, float t) {
    float xc = fminf(fmaxf(x, -CLIP_C), CLIP_C);
    float e  = __expf(-fabsf(xc));
    float sp = fmaxf(xc, 0.0f) + __logf(1.0f + e);
    return fmaf(-t, xc, sp);
}

__device__ __forceinline__ float fast_sigmoid(float x) {
    return 1.0f / (1.0f + __expf(-x));
}

__global__ void yolo_zero_kernel(float* out) { out[0] = 0.0f; }

template <int G>
__global__ __launch_bounds__(256)
void yolo_layer_kernel(const float* __restrict__ yp,
                       const float* __restrict__ yt,
                       const float* __restrict__ tgt,
                       float* __restrict__ out,
                       float aw0, float ah0,
                       float aw1, float ah1,
                       float aw2, float ah2)
{
    __shared__ float4 s_tgt[NBATCH * NBOX];   // 640 boxes * 16B = 10 KB
    __shared__ float  s_red[8];

    // Stage all target boxes (x,y,w,h) for all 32 batches into shared.
    for (int i = threadIdx.x; i < NBATCH * NBOX; i += 256) {
        const float* p = tgt + i * 5;
        s_tgt[i] = make_float4(p[0], p[1], p[2], p[3]);
    }
    __syncthreads();

    constexpr int GG    = G * G;
    constexpr int CELLS = NBATCH * 3 * GG;

    int idx = blockIdx.x * 256 + threadIdx.x;
    float lsum = 0.0f;

    if (idx < CELLS) {
        const int gx = idx % G;
        const int gy = (idx / G) % G;
        const int a  = (idx / GG) % 3;
        const int b  = idx / (3 * GG);

        const float aw = (a == 0) ? aw0 : ((a == 1) ? aw1 : aw2);
        const float ah = (a == 0) ? ah0 : ((a == 1) ? ah1 : ah2);

        const float* ypc = yp + ((size_t)(b * 255 + a * 85)) * GG + gy * G + gx;
        const float* ytc = yt + (size_t)idx * 85;

        // First 5 channels of pred (strided by GG, coalesced across warp)
        const float r0 = ypc[0 * GG];
        const float r1 = ypc[1 * GG];
        const float r2 = ypc[2 * GG];
        const float r3 = ypc[3 * GG];
        const float r4 = ypc[4 * GG];

        const float t0 = ytc[0];
        const float t1 = ytc[1];
        const float t2 = ytc[2];
        const float t3 = ytc[3];
        const float mask = ytc[4];

        // ---- decoded pred box (for IoU) ----
        const float sx = fast_sigmoid(r0);
        const float sy = fast_sigmoid(r1);
        const float inv_g = 1.0f / (float)G;
        const float bx = (sx + (float)gx) * inv_g;
        const float by = (sy + (float)gy) * inv_g;
        const float bw = __expf(r2) * (aw * (1.0f / 416.0f));
        const float bh = __expf(r3) * (ah * (1.0f / 416.0f));

        const float b1minx = bx - 0.5f * bw, b1maxx = bx + 0.5f * bw;
        const float b1miny = by - 0.5f * bh, b1maxy = by + 0.5f * bh;
        const float area1  = bw * bh;

        // ---- best IoU over 20 target boxes ----
        float best = 0.0f;
        const float4* tb = &s_tgt[b * NBOX];
        #pragma unroll
        for (int t = 0; t < NBOX; t++) {
            const float4 bb = tb[t];
            const float b2minx = bb.x - 0.5f * bb.z, b2maxx = bb.x + 0.5f * bb.z;
            const float b2miny = bb.y - 0.5f * bb.w, b2maxy = bb.y + 0.5f * bb.w;
            float iw = fminf(b1maxx, b2maxx) - fmaxf(b1minx, b2minx);
            float ih = fminf(b1maxy, b2maxy) - fmaxf(b1miny, b2miny);
            iw = fmaxf(iw, 0.0f);
            ih = fmaxf(ih, 0.0f);
            const float inter = iw * ih;
            const float iou = __fdividef(inter, area1 + bb.z * bb.w - inter);
            best = fmaxf(best, iou);
        }
        const float neg = (best < 0.5f) ? 1.0f : 0.0f;

        // ---- xy loss ----
        const float true_x = t0 * (float)G - (float)gx;
        const float true_y = t1 * (float)G - (float)gy;
        const float scale  = 2.0f - t2 * t3;
        const float ms     = mask * scale;
        float loss = ms * (bce_logit(r0, true_x) + bce_logit(r1, true_y));

        // ---- wh loss ----
        float tw = __logf(t2 * (416.0f / aw));
        float th = __logf(t3 * (416.0f / ah));
        if (!(mask > 0.0f)) { tw = 0.0f; th = 0.0f; }
        const float dw = r2 - tw, dh = r3 - th;
        loss += ms * 0.5f * (dw * dw + dh * dh);

        // ---- conf loss ----
        const float cb = bce_logit(r4, mask);
        loss += mask * cb + (1.0f - mask) * neg * cb;

        // ---- class loss (80 classes) ----
        float cls = 0.0f;
        #pragma unroll 8
        for (int c = 5; c < 85; c++) {
            const float x = ypc[c * GG];
            const float t = ytc[c];
            cls += bce_logit(x, t);
        }
        loss += mask * cls;

        lsum = loss;
    }

    // ---- block reduction ----
    #pragma unroll
    for (int o = 16; o > 0; o >>= 1)
        lsum += __shfl_down_sync(0xffffffffu, lsum, o);
    const int lane = threadIdx.x & 31;
    const int wid  = threadIdx.x >> 5;
    if (lane == 0) s_red[wid] = lsum;
    __syncthreads();
    if (wid == 0) {
        float v = (lane < 8) ? s_red[lane] : 0.0f;
        #pragma unroll
        for (int o = 4; o > 0; o >>= 1)
            v += __shfl_down_sync(0xffffffffu, v, o);
        if (lane == 0) atomicAdd(out, v);
    }
}

extern "C" void kernel_launch(void* const* d_in, const int* in_sizes, int n_in,
                              void* d_out, int out_size)
{
    // Interleaved order per setup_inputs() dict insertion
    const float* yp0 = (const float*)d_in[0];
    const float* yt0 = (const float*)d_in[1];
    const float* yp1 = (const float*)d_in[2];
    const float* yt1 = (const float*)d_in[3];
    const float* yp2 = (const float*)d_in[4];
    const float* yt2 = (const float*)d_in[5];
    const float* tgt = (const float*)d_in[6];
    float* out = (float*)d_out;

    yolo_zero_kernel<<<1, 1>>>(out);

    // Layer 0: G=13, anchors {6,7,8} = (116,90) (156,198) (373,326)
    {
        constexpr int cells = 32 * 3 * 13 * 13;
        yolo_layer_kernel<13><<<(cells + 255) / 256, 256>>>(
            yp0, yt0, tgt, out,
            116.0f, 90.0f, 156.0f, 198.0f, 373.0f, 326.0f);
    }
    // Layer 1: G=26, anchors {3,4,5} = (30,61) (62,45) (59,119)
    {
        constexpr int cells = 32 * 3 * 26 * 26;
        yolo_layer_kernel<26><<<(cells + 255) / 256, 256>>>(
            yp1, yt1, tgt, out,
            30.0f, 61.0f, 62.0f, 45.0f, 59.0f, 119.0f);
    }
    // Layer 2: G=52, anchors {0,1,2} = (10,13) (16,30) (33,23)
    {
        constexpr int cells = 32 * 3 * 52 * 52;
        yolo_layer_kernel<52><<<(cells + 255) / 256, 256>>>(
            yp2, yt2, tgt, out,
            10.0f, 13.0f, 16.0f, 30.0f, 33.0f, 23.0f);
    }
}

// round 3
// speedup vs baseline: 1.0931x; 1.0931x over previous
#include <cuda_runtime.h>
#include <math.h>

// ---------------------------------------------------------------------------
// YOLOv3 loss, fully fused (all 3 layers in one kernel), one scalar output.
// Input order (setup_inputs dict insertion order — interleaved):
//   d_in[0]=y_pred0 d_in[1]=y_true0 d_in[2]=y_pred1 d_in[3]=y_true1
//   d_in[4]=y_pred2 d_in[5]=y_true2 d_in[6]=target
// Layouts:
//   y_pred{i}: (32, 255, G, G)   float32 (channel-major)
//   y_true{i}: (32, 3, G, G, 85) float32 (channel-contiguous per cell)
//   target   : (32, 20, 5)       float32
// bce(sigmoid(x), t) == softplus(clamp(x,±C)) - t*clamp(x,±C),
//   C = ln((1-eps)/eps) = 16.118095 (exactly reproduces the eps p-clip)
//
// Key optimization: per-warp y_true staging. A warp's 32 cells cover a
// CONTIGUOUS 2720-float region of y_true (and every layer's cell count is a
// multiple of 32, so warps are all-active or all-inactive). Stage with
// coalesced float4 loads -> SMEM, consume at stride 85 (coprime with 32 ->
// bank-conflict-free). y_pred loads are natively coalesced (channel-major).
// ---------------------------------------------------------------------------

#define CLIP_C 16.118095f
#define NBOX   20
#define NBATCH 32

// block counts per layer (256 threads/block, one cell per thread)
#define NBLK2 1014   // 32*3*52*52 / 256 = 1014 (exact)
#define NBLK1 254    // ceil(32*3*26*26 / 256), tail is whole warps
#define NBLK0 64     // ceil(32*3*13*13 / 256), tail is whole warps
#define NBLK_TOTAL (NBLK2 + NBLK1 + NBLK0)

// smem layout (floats): y_true staging | targets | reduction
#define SYT_FLOATS (8 * 2720)          // 8 warps * 32 cells * 85 ch = 21760
#define STGT_OFF   SYT_FLOATS          // 640 float4 = 2560 floats
#define SRED_OFF   (SYT_FLOATS + 2560)
#define SMEM_FLOATS (SRED_OFF + 8)
#define SMEM_BYTES  (SMEM_FLOATS * 4)  // 97,344 B

__device__ __forceinline__ float bce_logit(float x, float t) {
    float xc = fminf(fmaxf(x, -CLIP_C), CLIP_C);
    float e  = __expf(-fabsf(xc));
    float sp = fmaxf(xc, 0.0f) + __logf(1.0f + e);
    return fmaf(-t, xc, sp);
}

__global__ void yolo_zero_kernel(float* out) { out[0] = 0.0f; }

__global__ __launch_bounds__(256)
void yolo_fused_kernel(const float* __restrict__ yp0, const float* __restrict__ yt0,
                       const float* __restrict__ yp1, const float* __restrict__ yt1,
                       const float* __restrict__ yp2, const float* __restrict__ yt2,
                       const float* __restrict__ tgt, float* __restrict__ out)
{
    extern __shared__ float smem[];
    float*  s_yt  = smem;
    float4* s_tgt = (float4*)(smem + STGT_OFF);
    float*  s_red = smem + SRED_OFF;

    const int tid  = threadIdx.x;
    const int lane = tid & 31;
    const int warp = tid >> 5;

    // Stage all target boxes (x,y,w,h) for all batches into shared.
    for (int i = tid; i < NBATCH * NBOX; i += 256) {
        const float* p = tgt + i * 5;
        s_tgt[i] = make_float4(p[0], p[1], p[2], p[3]);
    }
    __syncthreads();

    // ---- layer dispatch by block range (largest layer first) ----
    int bid = blockIdx.x;
    const float *yp, *yt;
    int G;
    float aw0, ah0, aw1, ah1, aw2, ah2;
    if (bid < NBLK2) {
        yp = yp2; yt = yt2; G = 52;
        aw0 = 10.f;  ah0 = 13.f;  aw1 = 16.f;  ah1 = 30.f;  aw2 = 33.f;  ah2 = 23.f;
    } else if (bid < NBLK2 + NBLK1) {
        bid -= NBLK2; yp = yp1; yt = yt1; G = 26;
        aw0 = 30.f;  ah0 = 61.f;  aw1 = 62.f;  ah1 = 45.f;  aw2 = 59.f;  ah2 = 119.f;
    } else {
        bid -= NBLK2 + NBLK1; yp = yp0; yt = yt0; G = 13;
        aw0 = 116.f; ah0 = 90.f;  aw1 = 156.f; ah1 = 198.f; aw2 = 373.f; ah2 = 326.f;
    }
    const int GG    = G * G;
    const int CELLS = NBATCH * 3 * GG;

    const int cellbase = bid * 256 + warp * 32;   // this warp's first cell
    float lsum = 0.0f;

    if (cellbase < CELLS) {   // whole-warp guard (all tails are warp multiples)
        // ---- stage this warp's y_true span: 2720 floats = 680 float4 ----
        float4*       s4  = (float4*)(s_yt + warp * 2720);
        const float4* src = (const float4*)(yt + (size_t)cellbase * 85);
        #pragma unroll
        for (int i = 0; i < 21; i++) s4[i * 32 + lane] = src[i * 32 + lane];
        if (lane < 8) s4[672 + lane] = src[672 + lane];
        __syncwarp();

        const int idx = cellbase + lane;
        const int gx  = idx % G;
        const int q1  = idx / G;
        const int gy  = q1 % G;
        const int q2  = q1 / G;          // b*3 + a
        const int a   = q2 % 3;
        const int b   = q2 / 3;

        const float aw = (a == 0) ? aw0 : ((a == 1) ? aw1 : aw2);
        const float ah = (a == 0) ? ah0 : ((a == 1) ? ah1 : ah2);

        const float* ypc = yp + ((size_t)(b * 255 + a * 85)) * GG + gy * G + gx;
        const float* ytc = s_yt + warp * 2720 + lane * 85;

        const float r0 = ypc[0 * GG];
        const float r1 = ypc[1 * GG];
        const float r2 = ypc[2 * GG];
        const float r3 = ypc[3 * GG];
        const float r4 = ypc[4 * GG];

        const float t0   = ytc[0];
        const float t1   = ytc[1];
        const float t2   = ytc[2];
        const float t3   = ytc[3];
        const float mask = ytc[4];

        // ---- decoded pred box (for IoU vs targets) ----
        const float sx = 1.0f / (1.0f + __expf(-r0));
        const float sy = 1.0f / (1.0f + __expf(-r1));
        const float inv_g = 1.0f / (float)G;
        const float bx = (sx + (float)gx) * inv_g;
        const float by = (sy + (float)gy) * inv_g;
        const float bw = __expf(r2) * (aw * (1.0f / 416.0f));
        const float bh = __expf(r3) * (ah * (1.0f / 416.0f));

        const float b1minx = bx - 0.5f * bw, b1maxx = bx + 0.5f * bw;
        const float b1miny = by - 0.5f * bh, b1maxy = by + 0.5f * bh;
        const float area1  = bw * bh;

        float best = 0.0f;
        const float4* tb = &s_tgt[b * NBOX];
        #pragma unroll
        for (int t = 0; t < NBOX; t++) {
            const float4 bb = tb[t];
            const float b2minx = bb.x - 0.5f * bb.z, b2maxx = bb.x + 0.5f * bb.z;
            const float b2miny = bb.y - 0.5f * bb.w, b2maxy = bb.y + 0.5f * bb.w;
            float iw = fminf(b1maxx, b2maxx) - fmaxf(b1minx, b2minx);
            float ih = fminf(b1maxy, b2maxy) - fmaxf(b1miny, b2miny);
            iw = fmaxf(iw, 0.0f);
            ih = fmaxf(ih, 0.0f);
            const float inter = iw * ih;
            const float iou = __fdividef(inter, area1 + bb.z * bb.w - inter);
            best = fmaxf(best, iou);
        }
        const float neg = (best < 0.5f) ? 1.0f : 0.0f;

        // ---- xy loss ----
        const float true_x = t0 * (float)G - (float)gx;
        const float true_y = t1 * (float)G - (float)gy;
        const float scale  = 2.0f - t2 * t3;
        const float ms     = mask * scale;
        float loss = ms * (bce_logit(r0, true_x) + bce_logit(r1, true_y));

        // ---- wh loss ----
        float tw = __logf(t2 * (416.0f / aw));
        float th = __logf(t3 * (416.0f / ah));
        if (!(mask > 0.0f)) { tw = 0.0f; th = 0.0f; }
        const float dw = r2 - tw, dh = r3 - th;
        loss += ms * 0.5f * (dw * dw + dh * dh);

        // ---- conf loss ----
        const float cb = bce_logit(r4, mask);
        loss += mask * cb + (1.0f - mask) * neg * cb;

        // ---- class loss (80 classes) ----
        float cls = 0.0f;
        #pragma unroll 8
        for (int c = 5; c < 85; c++) {
            cls += bce_logit(ypc[c * GG], ytc[c]);
        }
        loss += mask * cls;

        lsum = loss;
    }

    // ---- block reduction ----
    #pragma unroll
    for (int o = 16; o > 0; o >>= 1)
        lsum += __shfl_down_sync(0xffffffffu, lsum, o);
    if (lane == 0) s_red[warp] = lsum;
    __syncthreads();
    if (warp == 0) {
        float v = (lane < 8) ? s_red[lane] : 0.0f;
        #pragma unroll
        for (int o = 4; o > 0; o >>= 1)
            v += __shfl_down_sync(0xffffffffu, v, o);
        if (lane == 0) atomicAdd(out, v);
    }
}

extern "C" void kernel_launch(void* const* d_in, const int* in_sizes, int n_in,
                              void* d_out, int out_size)
{
    const float* yp0 = (const float*)d_in[0];
    const float* yt0 = (const float*)d_in[1];
    const float* yp1 = (const float*)d_in[2];
    const float* yt1 = (const float*)d_in[3];
    const float* yp2 = (const float*)d_in[4];
    const float* yt2 = (const float*)d_in[5];
    const float* tgt = (const float*)d_in[6];
    float* out = (float*)d_out;

    cudaFuncSetAttribute(yolo_fused_kernel,
                         cudaFuncAttributeMaxDynamicSharedMemorySize, SMEM_BYTES);

    yolo_zero_kernel<<<1, 1>>>(out);
    yolo_fused_kernel<<<NBLK_TOTAL, 256, SMEM_BYTES>>>(
        yp0, yt0, yp1, yt1, yp2, yt2, tgt, out);
}

// round 4
// speedup vs baseline: 1.3388x; 1.2248x over previous
#include <cuda_runtime.h>
#include <math.h>

// ---------------------------------------------------------------------------
// YOLOv3 loss, fully fused, one scalar output.
// d_in: [0]=y_pred0 [1]=y_true0 [2]=y_pred1 [3]=y_true1 [4]=y_pred2 [5]=y_true2 [6]=target
//   y_pred{i}: (32, 255, G, G)   float32 (channel-major)
//   y_true{i}: (32, 3, G, G, 85) float32 (channel-contiguous per cell)
//   target   : (32, 20, 5)       float32
// bce(sigmoid(x), t) == softplus(clamp(x,±C)) - t*clamp(x,±C), C=ln((1-eps)/eps)
//
// R4 scheme: per-warp HALF staging. 16 cells * 85 ch = 1360 floats = 5.44 KB.
// Two rounds per warp; 2 lanes per cell (lo lane: scalar losses + classes
// 5..44, hi lane: classes 45..84). smem = 8*5.44K + 40 target boxes ≈ 44.2 KB
// (static) -> 5 blocks/SM, 40 warps, vs 16 warps in R3.
// ---------------------------------------------------------------------------

#define CLIP_C 16.118095f
#define NBOX   20

#define NBLK2 1014   // 32*3*52*52/256
#define NBLK1 254    // ceil(32*3*26*26/256), tail = whole warps
#define NBLK0 64     // ceil(32*3*13*13/256), tail = whole warps
#define NBLK_TOTAL (NBLK2 + NBLK1 + NBLK0)

__device__ __forceinline__ float bce_logit(float x, float t) {
    float xc = fminf(fmaxf(x, -CLIP_C), CLIP_C);
    float e  = __expf(-fabsf(xc));
    float sp = fmaxf(xc, 0.0f) + __logf(1.0f + e);
    return fmaf(-t, xc, sp);
}

__global__ void yolo_zero_kernel(float* out) { out[0] = 0.0f; }

__global__ __launch_bounds__(256)
void yolo_fused_kernel(const float* __restrict__ yp0, const float* __restrict__ yt0,
                       const float* __restrict__ yp1, const float* __restrict__ yt1,
                       const float* __restrict__ yp2, const float* __restrict__ yt2,
                       const float* __restrict__ tgt, float* __restrict__ out)
{
    __shared__ float  s_yt[8 * 1360];   // 43,520 B
    __shared__ float4 s_tgt[2 * NBOX];  // 640 B (2 batches)
    __shared__ float  s_red[8];

    const int tid  = threadIdx.x;
    const int lane = tid & 31;
    const int warp = tid >> 5;
    const int half = lane >> 4;     // 0: scalar + classes 5..44, 1: classes 45..84
    const int li   = lane & 15;     // cell index within 16-cell round

    // ---- layer dispatch by block range (largest layer first) ----
    int bid = blockIdx.x;
    const float *yp, *yt;
    int G;
    float aw0, ah0, aw1, ah1, aw2, ah2;
    if (bid < NBLK2) {
        yp = yp2; yt = yt2; G = 52;
        aw0 = 10.f;  ah0 = 13.f;  aw1 = 16.f;  ah1 = 30.f;  aw2 = 33.f;  ah2 = 23.f;
    } else if (bid < NBLK2 + NBLK1) {
        bid -= NBLK2; yp = yp1; yt = yt1; G = 26;
        aw0 = 30.f;  ah0 = 61.f;  aw1 = 62.f;  ah1 = 45.f;  aw2 = 59.f;  ah2 = 119.f;
    } else {
        bid -= NBLK2 + NBLK1; yp = yp0; yt = yt0; G = 13;
        aw0 = 116.f; ah0 = 90.f;  aw1 = 156.f; ah1 = 198.f; aw2 = 373.f; ah2 = 326.f;
    }
    const int GG    = G * G;
    const int CELLS = 32 * 3 * GG;

    // ---- stage target boxes for the (<=2) batches this block touches ----
    const int bmin = min((bid * 256) / (3 * GG), 31);
    if (tid < 2 * NBOX) {
        int gbox = bmin * NBOX + tid;
        gbox = min(gbox, 32 * NBOX - 1);
        const float* p = tgt + gbox * 5;
        s_tgt[tid] = make_float4(p[0], p[1], p[2], p[3]);
    }
    __syncthreads();

    const int cellbase = bid * 256 + warp * 32;
    float lsum = 0.0f;

    if (cellbase < CELLS) {   // whole-warp guard (tails are warp multiples)
        float* s_buf = s_yt + warp * 1360;

        #pragma unroll
        for (int r = 0; r < 2; r++) {
            const int c16 = cellbase + r * 16;

            // ---- stage 16 cells of y_true: 1360 floats = 340 float4 ----
            // alignment: c16*85*4 bytes; c16 multiple of 16 -> 5440B multiple ✓
            float4*       dst = (float4*)s_buf;
            const float4* src = (const float4*)(yt + (size_t)c16 * 85);
            #pragma unroll
            for (int i = 0; i < 10; i++) dst[i * 32 + lane] = src[i * 32 + lane];
            if (lane < 20) dst[320 + lane] = src[320 + lane];
            __syncwarp();

            const int cell = c16 + li;
            const int gx   = cell % G;
            const int q1   = cell / G;
            const int gy   = q1 % G;
            const int q2   = q1 / G;       // b*3 + a
            const int a    = q2 % 3;
            const int b    = q2 / 3;

            const float aw = (a == 0) ? aw0 : ((a == 1) ? aw1 : aw2);
            const float ah = (a == 0) ? ah0 : ((a == 1) ? ah1 : ah2);

            const float* ypc = yp + ((size_t)(b * 255 + a * 85)) * GG + gy * G + gx;
            const float* ytc = s_buf + li * 85;
            const float mask = ytc[4];

            // ---- class loss: 40 channels per lane ----
            {
                const int cb = 5 + half * 40;
                float cls = 0.0f;
                #pragma unroll 8
                for (int j = 0; j < 40; j++)
                    cls += bce_logit(ypc[(cb + j) * GG], ytc[cb + j]);
                lsum += mask * cls;
            }

            // ---- scalar losses (lo half-lanes only) ----
            if (half == 0) {
                const float r0 = ypc[0 * GG];
                const float r1 = ypc[1 * GG];
                const float r2 = ypc[2 * GG];
                const float r3 = ypc[3 * GG];
                const float r4 = ypc[4 * GG];

                const float t0 = ytc[0];
                const float t1 = ytc[1];
                const float t2 = ytc[2];
                const float t3 = ytc[3];

                // decoded pred box
                const float sx = 1.0f / (1.0f + __expf(-r0));
                const float sy = 1.0f / (1.0f + __expf(-r1));
                const float inv_g = 1.0f / (float)G;
                const float bx = (sx + (float)gx) * inv_g;
                const float by = (sy + (float)gy) * inv_g;
                const float bw = __expf(r2) * (aw * (1.0f / 416.0f));
                const float bh = __expf(r3) * (ah * (1.0f / 416.0f));

                const float b1minx = bx - 0.5f * bw, b1maxx = bx + 0.5f * bw;
                const float b1miny = by - 0.5f * bh, b1maxy = by + 0.5f * bh;
                const float area1  = bw * bh;

                float best = 0.0f;
                const float4* tb = &s_tgt[(b - bmin) * NBOX];
                #pragma unroll
                for (int t = 0; t < NBOX; t++) {
                    const float4 bb = tb[t];
                    const float b2minx = bb.x - 0.5f * bb.z, b2maxx = bb.x + 0.5f * bb.z;
                    const float b2miny = bb.y - 0.5f * bb.w, b2maxy = bb.y + 0.5f * bb.w;
                    float iw = fminf(b1maxx, b2maxx) - fmaxf(b1minx, b2minx);
                    float ih = fminf(b1maxy, b2maxy) - fmaxf(b1miny, b2miny);
                    iw = fmaxf(iw, 0.0f);
                    ih = fmaxf(ih, 0.0f);
                    const float inter = iw * ih;
                    const float iou = __fdividef(inter, area1 + bb.z * bb.w - inter);
                    best = fmaxf(best, iou);
                }
                const float neg = (best < 0.5f) ? 1.0f : 0.0f;

                // xy
                const float true_x = t0 * (float)G - (float)gx;
                const float true_y = t1 * (float)G - (float)gy;
                const float scale  = 2.0f - t2 * t3;
                const float ms     = mask * scale;
                lsum += ms * (bce_logit(r0, true_x) + bce_logit(r1, true_y));

                // wh
                float tw = __logf(t2 * (416.0f / aw));
                float th = __logf(t3 * (416.0f / ah));
                if (!(mask > 0.0f)) { tw = 0.0f; th = 0.0f; }
                const float dw = r2 - tw, dh = r3 - th;
                lsum += ms * 0.5f * (dw * dw + dh * dh);

                // conf
                const float cb2 = bce_logit(r4, mask);
                lsum += mask * cb2 + (1.0f - mask) * neg * cb2;
            }
            __syncwarp();   // all LDS done before next round restages
        }
    }

    // ---- block reduction ----
    #pragma unroll
    for (int o = 16; o > 0; o >>= 1)
        lsum += __shfl_down_sync(0xffffffffu, lsum, o);
    if (lane == 0) s_red[warp] = lsum;
    __syncthreads();
    if (warp == 0) {
        float v = (lane < 8) ? s_red[lane] : 0.0f;
        #pragma unroll
        for (int o = 4; o > 0; o >>= 1)
            v += __shfl_down_sync(0xffffffffu, v, o);
        if (lane == 0) atomicAdd(out, v);
    }
}

extern "C" void kernel_launch(void* const* d_in, const int* in_sizes, int n_in,
                              void* d_out, int out_size)
{
    const float* yp0 = (const float*)d_in[0];
    const float* yt0 = (const float*)d_in[1];
    const float* yp1 = (const float*)d_in[2];
    const float* yt1 = (const float*)d_in[3];
    const float* yp2 = (const float*)d_in[4];
    const float* yt2 = (const float*)d_in[5];
    const float* tgt = (const float*)d_in[6];
    float* out = (float*)d_out;

    yolo_zero_kernel<<<1, 1>>>(out);
    yolo_fused_kernel<<<NBLK_TOTAL, 256>>>(
        yp0, yt0, yp1, yt1, yp2, yt2, tgt, out);
}